// round 9
// baseline (speedup 1.0000x reference)
#include <cuda_runtime.h>
#include <cuda_bf16.h>
#include <cstdint>

#define BB 256
#define CC 128
#define TT 64
#define H1 1024
#define H2 1024
#define NC 10

// Scratch device globals (allocation-free rule)
// s1 layout: [b*64+t][h1]  (m-index b-major so a GEMM tile spans all t)
__device__ __nv_bfloat16 g_s1h[(size_t)TT * BB * H1];    // 32MB
__device__ __nv_bfloat16 g_bsplit[(size_t)3 * H2 * H1];  // hid_w 3-way bf16 split (6MB)
__device__ uint32_t      g_bits[(size_t)TT * BB * 32];   // layer-2 spikes, bit-packed (2MB)

// ---------------------------------------------------------------------------
// helpers
// ---------------------------------------------------------------------------
__device__ __forceinline__ uint32_t smem_u32(const void* p) {
    uint32_t a;
    asm("{ .reg .u64 t; cvta.to.shared.u64 t, %1; cvt.u32.u64 %0, t; }"
        : "=r"(a) : "l"(p));
    return a;
}
__device__ __forceinline__ void cp_async16(uint32_t saddr, const void* gaddr) {
    asm volatile("cp.async.ca.shared.global [%0], [%1], 16;\n"
                 :: "r"(saddr), "l"(gaddr));
}
#define CP_COMMIT() asm volatile("cp.async.commit_group;\n" ::: "memory")
#define CP_WAIT(N)  asm volatile("cp.async.wait_group %0;\n" ::"n"(N) : "memory")

__device__ __forceinline__ void ldm_x4(uint32_t* r, uint32_t addr) {
    asm volatile("ldmatrix.sync.aligned.m8n8.x4.shared.b16 {%0,%1,%2,%3}, [%4];"
                 : "=r"(r[0]), "=r"(r[1]), "=r"(r[2]), "=r"(r[3]) : "r"(addr));
}
__device__ __forceinline__ void mma16816(float* c, const uint32_t* a,
                                         uint32_t b0, uint32_t b1) {
    asm volatile(
        "mma.sync.aligned.m16n8k16.row.col.f32.bf16.bf16.f32 "
        "{%0,%1,%2,%3}, {%4,%5,%6,%7}, {%8,%9}, {%0,%1,%2,%3};"
        : "+f"(c[0]), "+f"(c[1]), "+f"(c[2]), "+f"(c[3])
        : "r"(a[0]), "r"(a[1]), "r"(a[2]), "r"(a[3]), "r"(b0), "r"(b1));
}

// ---------------------------------------------------------------------------
// Kernel 0: split hid_w (fp32) into 3 bf16 limbs: w ~= b0 + b1 + b2 (~2^-27)
// ---------------------------------------------------------------------------
__global__ __launch_bounds__(256) void split_kernel(const float* __restrict__ w) {
    int i = blockIdx.x * 256 + threadIdx.x;
    float v = w[i];
    __nv_bfloat16 b0 = __float2bfloat16(v);
    float r1 = v - __bfloat162float(b0);
    __nv_bfloat16 b1 = __float2bfloat16(r1);
    float r2 = r1 - __bfloat162float(b1);
    __nv_bfloat16 b2 = __float2bfloat16(r2);
    g_bsplit[i] = b0;
    g_bsplit[(1 << 20) + i] = b1;
    g_bsplit[(2 << 20) + i] = b2;
}

// ---------------------------------------------------------------------------
// Kernel A: encoder + layer-1 IF scan (enc_w rows constant across channels ->
// rank-1: x @ enc_w^T = v_h * sum_c x[b,c,t]).  One block per batch element.
// Writes s1 in [b*64+t][h] layout.
// ---------------------------------------------------------------------------
__global__ __launch_bounds__(256) void enc_scan_kernel(
    const float* __restrict__ x, const float* __restrict__ enc_w,
    const float* __restrict__ enc_b) {
    __shared__ float S[TT];
    __shared__ float red[256];
    int b = blockIdx.x, tid = threadIdx.x;
    const float* xb = x + (size_t)b * CC * TT;
    int t = tid & 63, grp = tid >> 6;
    float a = 0.f;
#pragma unroll
    for (int c = 0; c < 32; c++) a += xb[(grp * 32 + c) * TT + t];
    red[tid] = a;
    __syncthreads();
    if (tid < 64) S[tid] = red[tid] + red[tid + 64] + red[tid + 128] + red[tid + 192];
    __syncthreads();

#pragma unroll
    for (int hh = 0; hh < 4; hh++) {
        int h = hh * 256 + tid;
        float vh = enc_w[(size_t)h * CC];
        float eb = enc_b[h];
        float v = 0.f;
#pragma unroll
        for (int tt = 0; tt < TT; tt++) {
            v += vh * S[tt] + eb;
            float s = (v >= 1.0f) ? 1.0f : 0.0f;
            g_s1h[(size_t)(((b << 6) + tt) << 10) + h] = __float2bfloat16(s);
            if (v >= 1.0f) v = 0.f;
        }
    }
}

// ---------------------------------------------------------------------------
// Kernel B: bf16 HMMA GEMM + fused layer-2 IF scan epilogue.
// C-rows m = b*64+t. BM=256 x BN=128, BK=16, 512 threads / 16 warps,
// warp grid 4m x 4n, warp tile 64x32 -> acc 64 regs/thread so the whole CTA
// fits the 64K-reg file with 16 warps (4/SMSP) resident. 3-stage cp.async
// pipeline, one syncthreads per chunk. Limb order per k16 identical to the
// previous round (bit-exact numerics).
// Epilogue: two 8-warp rounds; warp tile -> padded smem [64t][33], lane scans
// its h-column, ballot-packs into g_bits[t*256+b][word].
// ---------------------------------------------------------------------------
#define BM 256
#define BN 128
#define BK 16
#define A_BYTES (BM * 48)                    // 12288 (rows of 32B + 16B pad)
#define B_BYTES (BN * 48)                    // 6144 per limb
#define STAGE_BYTES (A_BYTES + 3 * B_BYTES)  // 30720
#define GEMM_SMEM (3 * STAGE_BYTES)          // 92160 (>= 8*8448 epilogue round)

__global__ __launch_bounds__(512, 1) void gemm2_kernel(const float* __restrict__ hid_b) {
    extern __shared__ __align__(128) char smem[];
    const uint32_t sb = smem_u32(smem);
    const int tid = threadIdx.x;
    const int wid = tid >> 5;
    const int lane = tid & 31;
    const int wm = wid >> 2;   // 0..3 -> m offset wm*64
    const int wn = wid & 3;    // 0..3 -> n offset wn*32
    const int m0 = blockIdx.y * BM;
    const int n0 = blockIdx.x * BN;

    const __nv_bfloat16* __restrict__ A = g_s1h;
    const __nv_bfloat16* __restrict__ Bw = g_bsplit;

    auto prefetch = [&](int chunk, int stage) {
        uint32_t as = sb + stage * STAGE_BYTES;
        uint32_t bs = as + A_BYTES;
        const __nv_bfloat16* ag = A + (size_t)m0 * 1024 + chunk * BK;
        {   // A: 256 rows x 2 x 16B = 512 tasks, one per thread
            int row = tid >> 1, c = tid & 1;
            cp_async16(as + row * 48 + c * 16, ag + (size_t)row * 1024 + c * 8);
        }
        // B: 3 limbs x 128 rows x 2 = 768 tasks
#pragma unroll
        for (int j = 0; j < 2; j++) {
            int id = tid + j * 512;
            if (id < 768) {
                int limb = id >> 8;
                int rem = id & 255;
                int nrow = rem >> 1, c = rem & 1;
                cp_async16(bs + limb * B_BYTES + nrow * 48 + c * 16,
                           Bw + ((size_t)limb << 20) + (size_t)(n0 + nrow) * 1024 +
                               chunk * BK + c * 8);
            }
        }
    };

    float acc[4][4][4];  // [mi][nblk][quad]
#pragma unroll
    for (int i = 0; i < 4; i++)
#pragma unroll
        for (int j = 0; j < 4; j++)
#pragma unroll
            for (int q = 0; q < 4; q++) acc[i][j][q] = 0.f;

    const int j8 = lane >> 3, r8 = lane & 7;
    const uint32_t a_off = ((j8 & 1) * 8 + r8) * 48 + (j8 >> 1) * 16;
    const uint32_t b_off = ((j8 >> 1) * 8 + r8) * 48 + (j8 & 1) * 16;

    prefetch(0, 0);
    CP_COMMIT();
    prefetch(1, 1);
    CP_COMMIT();

    for (int c = 0; c < 64; c++) {
        if (c < 63) { CP_WAIT(1); } else { CP_WAIT(0); }
        __syncthreads();

        const uint32_t as = sb + (c % 3) * STAGE_BYTES;
        const uint32_t bs = as + A_BYTES;

        uint32_t af[4][4];
#pragma unroll
        for (int mi = 0; mi < 4; mi++)
            ldm_x4(af[mi], as + (wm * 64 + mi * 16) * 48 + a_off);

#pragma unroll
        for (int limb = 0; limb < 3; limb++) {
#pragma unroll
            for (int p = 0; p < 2; p++) {  // 16 n-rows per ldm
                uint32_t bf[4];
                ldm_x4(bf, bs + limb * B_BYTES + (wn * 32 + p * 16) * 48 + b_off);
#pragma unroll
                for (int mi = 0; mi < 4; mi++) {
                    mma16816(acc[mi][2 * p], af[mi], bf[0], bf[1]);
                    mma16816(acc[mi][2 * p + 1], af[mi], bf[2], bf[3]);
                }
            }
        }

        if (c + 2 < 64) {
            prefetch(c + 2, (c + 2) % 3);
            CP_COMMIT();
        }
    }

    // ----- fused layer-2 IF scan epilogue (two 8-warp rounds) -----
    __syncthreads();
    const int b = blockIdx.y * 4 + wm;
    const int qrow = lane >> 2;
    const int qcol = (lane & 3) * 2;
    const int wordIdx = blockIdx.x * 4 + wn;  // (n0 + wn*32)/32
    const float hb = hid_b[n0 + wn * 32 + lane];

#pragma unroll
    for (int round = 0; round < 2; round++) {
        if ((wid >> 3) == round) {
            float* sw = reinterpret_cast<float*>(smem) + (size_t)(wid & 7) * (64 * 33);
#pragma unroll
            for (int mi = 0; mi < 4; mi++) {
                int t0 = mi * 16 + qrow;
#pragma unroll
                for (int nb = 0; nb < 4; nb++) {
                    int cc0 = nb * 8 + qcol;
                    sw[t0 * 33 + cc0]           = acc[mi][nb][0];
                    sw[t0 * 33 + cc0 + 1]       = acc[mi][nb][1];
                    sw[(t0 + 8) * 33 + cc0]     = acc[mi][nb][2];
                    sw[(t0 + 8) * 33 + cc0 + 1] = acc[mi][nb][3];
                }
            }
            __syncwarp();
            float v = 0.f;
#pragma unroll
            for (int t = 0; t < TT; t++) {
                v += sw[t * 33 + lane] + hb;
                bool fire = (v >= 1.0f);
                unsigned m = __ballot_sync(0xffffffffu, fire);
                if (lane == 0) g_bits[(size_t)((t << 8) + b) * 32 + wordIdx] = m;
                if (fire) v = 0.f;
            }
        }
        __syncthreads();
    }
}

// ---------------------------------------------------------------------------
// Kernel C: head — output GEMM (N=10) from bit-packed spikes + layer-3 IF
// scan + spike-rate.  One block per batch element.
// smem: ows[10*1024] f32 @0, bits[64][32] @40960, inp3[64][10] @49152
// ---------------------------------------------------------------------------
#define HEAD_SMEM (40960 + 8192 + 2560)

__global__ __launch_bounds__(256) void head_kernel(
    const float* __restrict__ out_w, const float* __restrict__ out_b,
    float* __restrict__ out) {
    extern __shared__ __align__(128) char hsm[];
    float* ows = reinterpret_cast<float*>(hsm);
    uint32_t* bitsm = reinterpret_cast<uint32_t*>(hsm + 40960);  // [t][word]
    float* inp3 = reinterpret_cast<float*>(hsm + 49152);         // [t][NC]

    const int b = blockIdx.x, tid = threadIdx.x;
    const int wid = tid >> 5, lane = tid & 31;

    for (int i = tid; i < NC * H2; i += 256) ows[i] = out_w[i];
#pragma unroll
    for (int j = 0; j < 8; j++) {
        int i = tid + j * 256;
        int t = i >> 5, k = i & 31;
        bitsm[i] = g_bits[(size_t)((t << 8) + b) * 32 + k];
    }
    __syncthreads();

    for (int tt = 0; tt < 8; tt++) {
        int t = wid * 8 + tt;
        float p[NC];
#pragma unroll
        for (int n = 0; n < NC; n++) p[n] = 0.f;
#pragma unroll
        for (int k = 0; k < 32; k++) {
            uint32_t w32 = bitsm[t * 32 + k];
            float s = (float)((w32 >> lane) & 1u);
            int i = k * 32 + lane;
#pragma unroll
            for (int n = 0; n < NC; n++) p[n] += s * ows[n * H2 + i];
        }
#pragma unroll
        for (int off = 16; off > 0; off >>= 1) {
#pragma unroll
            for (int n = 0; n < NC; n++)
                p[n] += __shfl_xor_sync(0xffffffffu, p[n], off);
        }
        if (lane == 0) {
#pragma unroll
            for (int n = 0; n < NC; n++) inp3[t * NC + n] = p[n];
        }
    }
    __syncthreads();

    if (tid < NC) {
        float ob = out_b[tid];
        float v = 0.f, cnt = 0.f;
#pragma unroll
        for (int t = 0; t < TT; t++) {
            v += inp3[t * NC + tid] + ob;
            if (v >= 1.0f) { cnt += 1.0f; v = 0.f; }
        }
        out[b * NC + tid] = cnt * (1.0f / (float)TT);
    }
}

// ---------------------------------------------------------------------------
extern "C" void kernel_launch(void* const* d_in, const int* in_sizes, int n_in,
                              void* d_out, int out_size) {
    const float* x     = (const float*)d_in[0];
    const float* enc_w = (const float*)d_in[1];
    const float* enc_b = (const float*)d_in[2];
    const float* hid_w = (const float*)d_in[3];
    const float* hid_b = (const float*)d_in[4];
    const float* out_w = (const float*)d_in[5];
    const float* out_b = (const float*)d_in[6];
    float* out = (float*)d_out;
    (void)in_sizes; (void)n_in; (void)out_size;

    cudaFuncSetAttribute(gemm2_kernel, cudaFuncAttributeMaxDynamicSharedMemorySize,
                         GEMM_SMEM);
    cudaFuncSetAttribute(head_kernel, cudaFuncAttributeMaxDynamicSharedMemorySize,
                         HEAD_SMEM);

    split_kernel<<<(H1 * H2) / 256, 256>>>(hid_w);
    enc_scan_kernel<<<BB, 256>>>(x, enc_w, enc_b);
    {
        dim3 grid(H2 / BN, (TT * BB) / BM);  // (8, 64)
        gemm2_kernel<<<grid, 512, GEMM_SMEM>>>(hid_b);
    }
    head_kernel<<<BB, 256, HEAD_SMEM>>>(out_w, out_b, out);
}

// round 10
// speedup vs baseline: 1.1279x; 1.1279x over previous
#include <cuda_runtime.h>
#include <cuda_bf16.h>
#include <cstdint>

#define BB 256
#define CC 128
#define TT 64
#define H1 1024
#define H2 1024
#define NC 10

// Scratch device globals (allocation-free rule)
// s1 layout: [b*64+t][h1]  (m-index b-major so a GEMM tile spans all t)
__device__ __nv_bfloat16 g_s1h[(size_t)TT * BB * H1];    // 32MB
__device__ __nv_bfloat16 g_bsplit[(size_t)3 * H2 * H1];  // hid_w 3-way bf16 split (6MB)
__device__ uint32_t      g_bits[(size_t)TT * BB * 32];   // layer-2 spikes, bit-packed (2MB)

// ---------------------------------------------------------------------------
// helpers
// ---------------------------------------------------------------------------
__device__ __forceinline__ uint32_t smem_u32(const void* p) {
    uint32_t a;
    asm("{ .reg .u64 t; cvta.to.shared.u64 t, %1; cvt.u32.u64 %0, t; }"
        : "=r"(a) : "l"(p));
    return a;
}
__device__ __forceinline__ void cp_async16(uint32_t saddr, const void* gaddr) {
    asm volatile("cp.async.ca.shared.global [%0], [%1], 16;\n"
                 :: "r"(saddr), "l"(gaddr));
}
#define CP_COMMIT() asm volatile("cp.async.commit_group;\n" ::: "memory")
#define CP_WAIT(N)  asm volatile("cp.async.wait_group %0;\n" ::"n"(N) : "memory")

__device__ __forceinline__ void ldm_x4(uint32_t* r, uint32_t addr) {
    asm volatile("ldmatrix.sync.aligned.m8n8.x4.shared.b16 {%0,%1,%2,%3}, [%4];"
                 : "=r"(r[0]), "=r"(r[1]), "=r"(r[2]), "=r"(r[3]) : "r"(addr));
}
__device__ __forceinline__ void mma16816(float* c, const uint32_t* a,
                                         uint32_t b0, uint32_t b1) {
    asm volatile(
        "mma.sync.aligned.m16n8k16.row.col.f32.bf16.bf16.f32 "
        "{%0,%1,%2,%3}, {%4,%5,%6,%7}, {%8,%9}, {%0,%1,%2,%3};"
        : "+f"(c[0]), "+f"(c[1]), "+f"(c[2]), "+f"(c[3])
        : "r"(a[0]), "r"(a[1]), "r"(a[2]), "r"(a[3]), "r"(b0), "r"(b1));
}

// ---------------------------------------------------------------------------
// Kernel 0: split hid_w (fp32) into 3 bf16 limbs: w ~= b0 + b1 + b2 (~2^-27)
// ---------------------------------------------------------------------------
__global__ __launch_bounds__(256) void split_kernel(const float* __restrict__ w) {
    int i = blockIdx.x * 256 + threadIdx.x;
    float v = w[i];
    __nv_bfloat16 b0 = __float2bfloat16(v);
    float r1 = v - __bfloat162float(b0);
    __nv_bfloat16 b1 = __float2bfloat16(r1);
    float r2 = r1 - __bfloat162float(b1);
    __nv_bfloat16 b2 = __float2bfloat16(r2);
    g_bsplit[i] = b0;
    g_bsplit[(1 << 20) + i] = b1;
    g_bsplit[(2 << 20) + i] = b2;
}

// ---------------------------------------------------------------------------
// Kernel A: encoder + layer-1 IF scan (enc_w rows constant across channels ->
// rank-1: x @ enc_w^T = v_h * sum_c x[b,c,t]).  One block per batch element.
// Writes s1 in [b*64+t][h] layout.
// ---------------------------------------------------------------------------
__global__ __launch_bounds__(256) void enc_scan_kernel(
    const float* __restrict__ x, const float* __restrict__ enc_w,
    const float* __restrict__ enc_b) {
    __shared__ float S[TT];
    __shared__ float red[256];
    int b = blockIdx.x, tid = threadIdx.x;
    const float* xb = x + (size_t)b * CC * TT;
    int t = tid & 63, grp = tid >> 6;
    float a = 0.f;
#pragma unroll
    for (int c = 0; c < 32; c++) a += xb[(grp * 32 + c) * TT + t];
    red[tid] = a;
    __syncthreads();
    if (tid < 64) S[tid] = red[tid] + red[tid + 64] + red[tid + 128] + red[tid + 192];
    __syncthreads();

#pragma unroll
    for (int hh = 0; hh < 4; hh++) {
        int h = hh * 256 + tid;
        float vh = enc_w[(size_t)h * CC];
        float eb = enc_b[h];
        float v = 0.f;
#pragma unroll
        for (int tt = 0; tt < TT; tt++) {
            v += vh * S[tt] + eb;
            float s = (v >= 1.0f) ? 1.0f : 0.0f;
            g_s1h[(size_t)(((b << 6) + tt) << 10) + h] = __float2bfloat16(s);
            if (v >= 1.0f) v = 0.f;
        }
    }
}

// ---------------------------------------------------------------------------
// Kernel B: bf16 HMMA GEMM + fused layer-2 IF scan epilogue. (R7 config)
// C-rows m = b*64+t. BM=256 x BN=128, BK=32, 256 threads / 8 warps (64x64).
// 3-stage cp.async pipeline, one syncthreads per chunk.
// Epilogue: warp tile -> padded smem [64t][65], lane scans its h-column,
// ballot-packs into g_bits[t*256+b][word].
// ---------------------------------------------------------------------------
#define BM 256
#define BN 128
#define BK 32
#define A_BYTES (BM * 40 * 2)                // 20480
#define B_BYTES (BN * 40 * 2)                // 10240 per limb
#define STAGE_BYTES (A_BYTES + 3 * B_BYTES)  // 51200
#define GEMM_SMEM (3 * STAGE_BYTES)          // 153600  (>= 8*16640 epilogue)

__global__ __launch_bounds__(256, 1) void gemm2_kernel(const float* __restrict__ hid_b) {
    extern __shared__ __align__(128) char smem[];
    const uint32_t sb = smem_u32(smem);
    const int tid = threadIdx.x;
    const int wid = tid >> 5;
    const int lane = tid & 31;
    const int wm = wid >> 1;
    const int wn = wid & 1;
    const int m0 = blockIdx.y * BM;
    const int n0 = blockIdx.x * BN;

    const __nv_bfloat16* __restrict__ A = g_s1h;
    const __nv_bfloat16* __restrict__ Bw = g_bsplit;

    auto prefetch = [&](int chunk, int stage) {
        uint32_t as = sb + stage * STAGE_BYTES;
        uint32_t bs = as + A_BYTES;
        const __nv_bfloat16* ag = A + (size_t)m0 * 1024 + chunk * BK;
#pragma unroll
        for (int j = 0; j < 4; j++) {
            int id = tid + j * 256;
            int row = id >> 2, c = id & 3;
            cp_async16(as + row * 80 + c * 16, ag + (size_t)row * 1024 + c * 8);
        }
#pragma unroll
        for (int j = 0; j < 6; j++) {
            int id = tid + j * 256;
            int limb = id >> 9;
            int rem = id & 511;
            int nrow = rem >> 2, c = rem & 3;
            cp_async16(bs + limb * B_BYTES + nrow * 80 + c * 16,
                       Bw + ((size_t)limb << 20) + (size_t)(n0 + nrow) * 1024 +
                           chunk * BK + c * 8);
        }
    };

    float acc[4][8][4];
#pragma unroll
    for (int i = 0; i < 4; i++)
#pragma unroll
        for (int j = 0; j < 8; j++)
#pragma unroll
            for (int q = 0; q < 4; q++) acc[i][j][q] = 0.f;

    const int j8 = lane >> 3, r8 = lane & 7;
    const uint32_t a_off = ((j8 & 1) * 8 + r8) * 80 + (j8 >> 1) * 16;
    const uint32_t b_off = ((j8 >> 1) * 8 + r8) * 80 + (j8 & 1) * 16;

    prefetch(0, 0);
    CP_COMMIT();
    prefetch(1, 1);
    CP_COMMIT();

    for (int c = 0; c < 32; c++) {
        if (c < 31) { CP_WAIT(1); } else { CP_WAIT(0); }
        __syncthreads();

        const uint32_t as = sb + (c % 3) * STAGE_BYTES;
        const uint32_t bs = as + A_BYTES;

#pragma unroll
        for (int ks = 0; ks < 2; ks++) {
            uint32_t af[4][4];
#pragma unroll
            for (int mi = 0; mi < 4; mi++)
                ldm_x4(af[mi], as + (wm * 64 + mi * 16) * 80 + ks * 32 + a_off);
#pragma unroll
            for (int limb = 0; limb < 3; limb++) {
                uint32_t bf[4][4];
#pragma unroll
                for (int p = 0; p < 4; p++)
                    ldm_x4(bf[p], bs + limb * B_BYTES +
                                      (wn * 64 + p * 16) * 80 + ks * 32 + b_off);
#pragma unroll
                for (int mi = 0; mi < 4; mi++)
#pragma unroll
                    for (int p = 0; p < 4; p++) {
                        mma16816(acc[mi][2 * p], af[mi], bf[p][0], bf[p][1]);
                        mma16816(acc[mi][2 * p + 1], af[mi], bf[p][2], bf[p][3]);
                    }
            }
        }

        if (c + 2 < 32) {
            prefetch(c + 2, (c + 2) % 3);
            CP_COMMIT();
        }
    }

    // ----- fused layer-2 IF scan epilogue -----
    __syncthreads();  // all warps done reading pipeline buffers
    float* sw = reinterpret_cast<float*>(smem) + (size_t)wid * (64 * 65);
    const int qrow = lane >> 2;
    const int qcol = (lane & 3) * 2;
#pragma unroll
    for (int mi = 0; mi < 4; mi++) {
        int t0 = mi * 16 + qrow;
#pragma unroll
        for (int ni = 0; ni < 8; ni++) {
            int cc0 = ni * 8 + qcol;
            sw[t0 * 65 + cc0]       = acc[mi][ni][0];
            sw[t0 * 65 + cc0 + 1]   = acc[mi][ni][1];
            sw[(t0 + 8) * 65 + cc0]     = acc[mi][ni][2];
            sw[(t0 + 8) * 65 + cc0 + 1] = acc[mi][ni][3];
        }
    }
    __syncwarp();

    const int b = blockIdx.y * 4 + wm;
#pragma unroll
    for (int grp = 0; grp < 2; grp++) {
        int h = n0 + wn * 64 + grp * 32 + lane;
        float hb = hid_b[h];
        int wordIdx = ((n0 + wn * 64) >> 5) + grp;  // 0..31
        float v = 0.f;
#pragma unroll
        for (int t = 0; t < TT; t++) {
            v += sw[t * 65 + grp * 32 + lane] + hb;
            bool fire = (v >= 1.0f);
            unsigned m = __ballot_sync(0xffffffffu, fire);
            if (lane == 0) g_bits[(size_t)((t << 8) + b) * 32 + wordIdx] = m;
            if (fire) v = 0.f;
        }
    }
}

// ---------------------------------------------------------------------------
// Kernel C: head — output GEMM from bit-packed spikes + layer-3 IF scan +
// spike-rate.  Class-split: grid (256 b, 2 halves of 5 classes).  Each block
// stages only its 5 out_w rows (20 KB) -> half the LDS traffic per block and
// 512 CTAs for occupancy.  Per-(t,n) math identical to the unsplit version.
// smem: ows[5*1024] f32 @0, bits[64][32] @20480, inp3[64][5] @28672
// ---------------------------------------------------------------------------
#define NCH 5
#define HEAD_SMEM (20480 + 8192 + 1280)

__global__ __launch_bounds__(256) void head_kernel(
    const float* __restrict__ out_w, const float* __restrict__ out_b,
    float* __restrict__ out) {
    extern __shared__ __align__(128) char hsm[];
    float* ows = reinterpret_cast<float*>(hsm);                  // [5][1024]
    uint32_t* bitsm = reinterpret_cast<uint32_t*>(hsm + 20480);  // [t][word]
    float* inp3 = reinterpret_cast<float*>(hsm + 28672);         // [t][5]

    const int b = blockIdx.x, nh = blockIdx.y, tid = threadIdx.x;
    const int wid = tid >> 5, lane = tid & 31;

    for (int i = tid; i < NCH * H2; i += 256) ows[i] = out_w[nh * NCH * H2 + i];
#pragma unroll
    for (int j = 0; j < 8; j++) {
        int i = tid + j * 256;
        int t = i >> 5, k = i & 31;
        bitsm[i] = g_bits[(size_t)((t << 8) + b) * 32 + k];
    }
    __syncthreads();

    for (int tt = 0; tt < 8; tt++) {
        int t = wid * 8 + tt;
        float p[NCH];
#pragma unroll
        for (int n = 0; n < NCH; n++) p[n] = 0.f;
#pragma unroll
        for (int k = 0; k < 32; k++) {
            uint32_t w32 = bitsm[t * 32 + k];
            float s = (float)((w32 >> lane) & 1u);
            int i = k * 32 + lane;
#pragma unroll
            for (int n = 0; n < NCH; n++) p[n] += s * ows[n * H2 + i];
        }
#pragma unroll
        for (int off = 16; off > 0; off >>= 1) {
#pragma unroll
            for (int n = 0; n < NCH; n++)
                p[n] += __shfl_xor_sync(0xffffffffu, p[n], off);
        }
        if (lane == 0) {
#pragma unroll
            for (int n = 0; n < NCH; n++) inp3[t * NCH + n] = p[n];
        }
    }
    __syncthreads();

    if (tid < NCH) {
        float ob = out_b[nh * NCH + tid];
        float v = 0.f, cnt = 0.f;
#pragma unroll
        for (int t = 0; t < TT; t++) {
            v += inp3[t * NCH + tid] + ob;
            if (v >= 1.0f) { cnt += 1.0f; v = 0.f; }
        }
        out[b * NC + nh * NCH + tid] = cnt * (1.0f / (float)TT);
    }
}

// ---------------------------------------------------------------------------
extern "C" void kernel_launch(void* const* d_in, const int* in_sizes, int n_in,
                              void* d_out, int out_size) {
    const float* x     = (const float*)d_in[0];
    const float* enc_w = (const float*)d_in[1];
    const float* enc_b = (const float*)d_in[2];
    const float* hid_w = (const float*)d_in[3];
    const float* hid_b = (const float*)d_in[4];
    const float* out_w = (const float*)d_in[5];
    const float* out_b = (const float*)d_in[6];
    float* out = (float*)d_out;
    (void)in_sizes; (void)n_in; (void)out_size;

    cudaFuncSetAttribute(gemm2_kernel, cudaFuncAttributeMaxDynamicSharedMemorySize,
                         GEMM_SMEM);
    cudaFuncSetAttribute(head_kernel, cudaFuncAttributeMaxDynamicSharedMemorySize,
                         HEAD_SMEM);

    split_kernel<<<(H1 * H2) / 256, 256>>>(hid_w);
    enc_scan_kernel<<<BB, 256>>>(x, enc_w, enc_b);
    {
        dim3 grid(H2 / BN, (TT * BB) / BM);  // (8, 64)
        gemm2_kernel<<<grid, 256, GEMM_SMEM>>>(hid_b);
    }
    {
        dim3 hgrid(BB, NC / NCH);  // (256, 2)
        head_kernel<<<hgrid, 256, HEAD_SMEM>>>(out_w, out_b, out);
    }
}

// round 11
// speedup vs baseline: 1.4918x; 1.3226x over previous
#include <cuda_runtime.h>
#include <cuda_fp16.h>
#include <cstdint>

#define BB 256
#define CC 128
#define TT 64
#define H1 1024
#define H2 1024
#define NC 10

// Scratch device globals (allocation-free rule)
// s1 layout: [b*64+t][h1]  (m-index b-major so a GEMM tile spans all t)
__device__ __half    g_s1h[(size_t)TT * BB * H1];      // 32MB, fp16 spikes {0,1}
__device__ __half    g_wsplit[(size_t)2 * H2 * H1];    // hid_w 2-way fp16 split (4MB)
__device__ uint32_t  g_bits[(size_t)TT * BB * 32];     // layer-2 spikes, bit-packed (2MB)

// ---------------------------------------------------------------------------
// helpers
// ---------------------------------------------------------------------------
__device__ __forceinline__ uint32_t smem_u32(const void* p) {
    uint32_t a;
    asm("{ .reg .u64 t; cvta.to.shared.u64 t, %1; cvt.u32.u64 %0, t; }"
        : "=r"(a) : "l"(p));
    return a;
}
__device__ __forceinline__ void cp_async16(uint32_t saddr, const void* gaddr) {
    asm volatile("cp.async.ca.shared.global [%0], [%1], 16;\n"
                 :: "r"(saddr), "l"(gaddr));
}
#define CP_COMMIT() asm volatile("cp.async.commit_group;\n" ::: "memory")
#define CP_WAIT(N)  asm volatile("cp.async.wait_group %0;\n" ::"n"(N) : "memory")

__device__ __forceinline__ void ldm_x4(uint32_t* r, uint32_t addr) {
    asm volatile("ldmatrix.sync.aligned.m8n8.x4.shared.b16 {%0,%1,%2,%3}, [%4];"
                 : "=r"(r[0]), "=r"(r[1]), "=r"(r[2]), "=r"(r[3]) : "r"(addr));
}
__device__ __forceinline__ void mma16816(float* c, const uint32_t* a,
                                         uint32_t b0, uint32_t b1) {
    asm volatile(
        "mma.sync.aligned.m16n8k16.row.col.f32.f16.f16.f32 "
        "{%0,%1,%2,%3}, {%4,%5,%6,%7}, {%8,%9}, {%0,%1,%2,%3};"
        : "+f"(c[0]), "+f"(c[1]), "+f"(c[2]), "+f"(c[3])
        : "r"(a[0]), "r"(a[1]), "r"(a[2]), "r"(a[3]), "r"(b0), "r"(b1));
}

// ---------------------------------------------------------------------------
// Kernel 0: split hid_w (fp32) into 2 fp16 limbs: w ~= b0 + b1  (~2^-22 rel,
// subnormal b1 lattice adds <=2^-25 abs — below fp32-accumulation noise)
// ---------------------------------------------------------------------------
__global__ __launch_bounds__(256) void split_kernel(const float* __restrict__ w) {
    int i = blockIdx.x * 256 + threadIdx.x;
    float v = w[i];
    __half b0 = __float2half_rn(v);
    float r1 = v - __half2float(b0);
    __half b1 = __float2half_rn(r1);
    g_wsplit[i] = b0;
    g_wsplit[(1 << 20) + i] = b1;
}

// ---------------------------------------------------------------------------
// Kernel A: encoder + layer-1 IF scan (enc_w rows constant across channels ->
// rank-1: x @ enc_w^T = v_h * sum_c x[b,c,t]).  One block per batch element.
// Writes s1 in [b*64+t][h] layout, fp16 {0,1}.
// ---------------------------------------------------------------------------
__global__ __launch_bounds__(256) void enc_scan_kernel(
    const float* __restrict__ x, const float* __restrict__ enc_w,
    const float* __restrict__ enc_b) {
    __shared__ float S[TT];
    __shared__ float red[256];
    int b = blockIdx.x, tid = threadIdx.x;
    const float* xb = x + (size_t)b * CC * TT;
    int t = tid & 63, grp = tid >> 6;
    float a = 0.f;
#pragma unroll
    for (int c = 0; c < 32; c++) a += xb[(grp * 32 + c) * TT + t];
    red[tid] = a;
    __syncthreads();
    if (tid < 64) S[tid] = red[tid] + red[tid + 64] + red[tid + 128] + red[tid + 192];
    __syncthreads();

#pragma unroll
    for (int hh = 0; hh < 4; hh++) {
        int h = hh * 256 + tid;
        float vh = enc_w[(size_t)h * CC];
        float eb = enc_b[h];
        float v = 0.f;
#pragma unroll
        for (int tt = 0; tt < TT; tt++) {
            v += vh * S[tt] + eb;
            float s = (v >= 1.0f) ? 1.0f : 0.0f;
            g_s1h[(size_t)(((b << 6) + tt) << 10) + h] = __float2half_rn(s);
            if (v >= 1.0f) v = 0.f;
        }
    }
}

// ---------------------------------------------------------------------------
// Kernel B: fp16 HMMA GEMM + fused layer-2 IF scan epilogue.
// C-rows m = b*64+t. BM=256 x BN=128, BK=32, 256 threads / 8 warps (64x64).
// 2 fp16 weight limbs (was 3 bf16) -> 2/3 the MMA work.
// 3-stage cp.async pipeline, one syncthreads per chunk.
// Epilogue: warp tile -> padded smem [64t][65], lane scans its h-column,
// ballot-packs into g_bits[t*256+b][word].
// ---------------------------------------------------------------------------
#define BM 256
#define BN 128
#define BK 32
#define A_BYTES (BM * 40 * 2)                // 20480
#define B_BYTES (BN * 40 * 2)                // 10240 per limb
#define STAGE_BYTES (A_BYTES + 2 * B_BYTES)  // 40960
#define GEMM_SMEM 133120                     // max(3*STAGE_BYTES, 8*64*65*4)

__global__ __launch_bounds__(256, 1) void gemm2_kernel(const float* __restrict__ hid_b) {
    extern __shared__ __align__(128) char smem[];
    const uint32_t sb = smem_u32(smem);
    const int tid = threadIdx.x;
    const int wid = tid >> 5;
    const int lane = tid & 31;
    const int wm = wid >> 1;
    const int wn = wid & 1;
    const int m0 = blockIdx.y * BM;
    const int n0 = blockIdx.x * BN;

    const __half* __restrict__ A = g_s1h;
    const __half* __restrict__ Bw = g_wsplit;

    auto prefetch = [&](int chunk, int stage) {
        uint32_t as = sb + stage * STAGE_BYTES;
        uint32_t bs = as + A_BYTES;
        const __half* ag = A + (size_t)m0 * 1024 + chunk * BK;
#pragma unroll
        for (int j = 0; j < 4; j++) {
            int id = tid + j * 256;
            int row = id >> 2, c = id & 3;
            cp_async16(as + row * 80 + c * 16, ag + (size_t)row * 1024 + c * 8);
        }
        // B: 2 limbs x 128 rows x 4 chunks = 1024 tasks, 4/thread
#pragma unroll
        for (int j = 0; j < 4; j++) {
            int id = tid + j * 256;
            int limb = id >> 9;
            int rem = id & 511;
            int nrow = rem >> 2, c = rem & 3;
            cp_async16(bs + limb * B_BYTES + nrow * 80 + c * 16,
                       Bw + ((size_t)limb << 20) + (size_t)(n0 + nrow) * 1024 +
                           chunk * BK + c * 8);
        }
    };

    float acc[4][8][4];
#pragma unroll
    for (int i = 0; i < 4; i++)
#pragma unroll
        for (int j = 0; j < 8; j++)
#pragma unroll
            for (int q = 0; q < 4; q++) acc[i][j][q] = 0.f;

    const int j8 = lane >> 3, r8 = lane & 7;
    const uint32_t a_off = ((j8 & 1) * 8 + r8) * 80 + (j8 >> 1) * 16;
    const uint32_t b_off = ((j8 >> 1) * 8 + r8) * 80 + (j8 & 1) * 16;

    prefetch(0, 0);
    CP_COMMIT();
    prefetch(1, 1);
    CP_COMMIT();

    for (int c = 0; c < 32; c++) {
        if (c < 31) { CP_WAIT(1); } else { CP_WAIT(0); }
        __syncthreads();

        const uint32_t as = sb + (c % 3) * STAGE_BYTES;
        const uint32_t bs = as + A_BYTES;

#pragma unroll
        for (int ks = 0; ks < 2; ks++) {
            uint32_t af[4][4];
#pragma unroll
            for (int mi = 0; mi < 4; mi++)
                ldm_x4(af[mi], as + (wm * 64 + mi * 16) * 80 + ks * 32 + a_off);
#pragma unroll
            for (int limb = 0; limb < 2; limb++) {
                uint32_t bf[4][4];
#pragma unroll
                for (int p = 0; p < 4; p++)
                    ldm_x4(bf[p], bs + limb * B_BYTES +
                                      (wn * 64 + p * 16) * 80 + ks * 32 + b_off);
#pragma unroll
                for (int mi = 0; mi < 4; mi++)
#pragma unroll
                    for (int p = 0; p < 4; p++) {
                        mma16816(acc[mi][2 * p], af[mi], bf[p][0], bf[p][1]);
                        mma16816(acc[mi][2 * p + 1], af[mi], bf[p][2], bf[p][3]);
                    }
            }
        }

        if (c + 2 < 32) {
            prefetch(c + 2, (c + 2) % 3);
            CP_COMMIT();
        }
    }

    // ----- fused layer-2 IF scan epilogue -----
    __syncthreads();  // all warps done reading pipeline buffers
    float* sw = reinterpret_cast<float*>(smem) + (size_t)wid * (64 * 65);
    const int qrow = lane >> 2;
    const int qcol = (lane & 3) * 2;
#pragma unroll
    for (int mi = 0; mi < 4; mi++) {
        int t0 = mi * 16 + qrow;
#pragma unroll
        for (int ni = 0; ni < 8; ni++) {
            int cc0 = ni * 8 + qcol;
            sw[t0 * 65 + cc0]       = acc[mi][ni][0];
            sw[t0 * 65 + cc0 + 1]   = acc[mi][ni][1];
            sw[(t0 + 8) * 65 + cc0]     = acc[mi][ni][2];
            sw[(t0 + 8) * 65 + cc0 + 1] = acc[mi][ni][3];
        }
    }
    __syncwarp();

    const int b = blockIdx.y * 4 + wm;
#pragma unroll
    for (int grp = 0; grp < 2; grp++) {
        int h = n0 + wn * 64 + grp * 32 + lane;
        float hb = hid_b[h];
        int wordIdx = ((n0 + wn * 64) >> 5) + grp;  // 0..31
        float v = 0.f;
#pragma unroll
        for (int t = 0; t < TT; t++) {
            v += sw[t * 65 + grp * 32 + lane] + hb;
            bool fire = (v >= 1.0f);
            unsigned m = __ballot_sync(0xffffffffu, fire);
            if (lane == 0) g_bits[(size_t)((t << 8) + b) * 32 + wordIdx] = m;
            if (fire) v = 0.f;
        }
    }
}

// ---------------------------------------------------------------------------
// Kernel C: head — output GEMM from bit-packed spikes + layer-3 IF scan +
// spike-rate.  Class-split grid (256 b, 2 halves of 5).  Phase 2 is k-outer:
// ows values loaded once per k and reused across the warp's 8 timesteps
// (per-(t,n) accumulation order identical to the t-outer version).
// smem: ows[5*1024] f32 @0, bits[64][32] @20480, inp3[64][5] @28672
// ---------------------------------------------------------------------------
#define NCH 5
#define HEAD_SMEM (20480 + 8192 + 1280)

__global__ __launch_bounds__(256) void head_kernel(
    const float* __restrict__ out_w, const float* __restrict__ out_b,
    float* __restrict__ out) {
    extern __shared__ __align__(128) char hsm[];
    float* ows = reinterpret_cast<float*>(hsm);                  // [5][1024]
    uint32_t* bitsm = reinterpret_cast<uint32_t*>(hsm + 20480);  // [t][word]
    float* inp3 = reinterpret_cast<float*>(hsm + 28672);         // [t][5]

    const int b = blockIdx.x, nh = blockIdx.y, tid = threadIdx.x;
    const int wid = tid >> 5, lane = tid & 31;

    for (int i = tid; i < NCH * H2; i += 256) ows[i] = out_w[nh * NCH * H2 + i];
#pragma unroll
    for (int j = 0; j < 8; j++) {
        int i = tid + j * 256;
        int t = i >> 5, k = i & 31;
        bitsm[i] = g_bits[(size_t)((t << 8) + b) * 32 + k];
    }
    __syncthreads();

    // k-outer: p[tt][n] accumulates over k ascending (same order as before)
    float p[8][NCH];
#pragma unroll
    for (int tt = 0; tt < 8; tt++)
#pragma unroll
        for (int n = 0; n < NCH; n++) p[tt][n] = 0.f;

#pragma unroll 4
    for (int k = 0; k < 32; k++) {
        float w[NCH];
        int i = k * 32 + lane;
#pragma unroll
        for (int n = 0; n < NCH; n++) w[n] = ows[n * H2 + i];
#pragma unroll
        for (int tt = 0; tt < 8; tt++) {
            uint32_t w32 = bitsm[(wid * 8 + tt) * 32 + k];
            float s = (float)((w32 >> lane) & 1u);
#pragma unroll
            for (int n = 0; n < NCH; n++) p[tt][n] += s * w[n];
        }
    }

#pragma unroll
    for (int tt = 0; tt < 8; tt++) {
#pragma unroll
        for (int off = 16; off > 0; off >>= 1) {
#pragma unroll
            for (int n = 0; n < NCH; n++)
                p[tt][n] += __shfl_xor_sync(0xffffffffu, p[tt][n], off);
        }
        if (lane == 0) {
#pragma unroll
            for (int n = 0; n < NCH; n++)
                inp3[(wid * 8 + tt) * NCH + n] = p[tt][n];
        }
    }
    __syncthreads();

    if (tid < NCH) {
        float ob = out_b[nh * NCH + tid];
        float v = 0.f, cnt = 0.f;
#pragma unroll
        for (int t = 0; t < TT; t++) {
            v += inp3[t * NCH + tid] + ob;
            if (v >= 1.0f) { cnt += 1.0f; v = 0.f; }
        }
        out[b * NC + nh * NCH + tid] = cnt * (1.0f / (float)TT);
    }
}

// ---------------------------------------------------------------------------
extern "C" void kernel_launch(void* const* d_in, const int* in_sizes, int n_in,
                              void* d_out, int out_size) {
    const float* x     = (const float*)d_in[0];
    const float* enc_w = (const float*)d_in[1];
    const float* enc_b = (const float*)d_in[2];
    const float* hid_w = (const float*)d_in[3];
    const float* hid_b = (const float*)d_in[4];
    const float* out_w = (const float*)d_in[5];
    const float* out_b = (const float*)d_in[6];
    float* out = (float*)d_out;
    (void)in_sizes; (void)n_in; (void)out_size;

    cudaFuncSetAttribute(gemm2_kernel, cudaFuncAttributeMaxDynamicSharedMemorySize,
                         GEMM_SMEM);
    cudaFuncSetAttribute(head_kernel, cudaFuncAttributeMaxDynamicSharedMemorySize,
                         HEAD_SMEM);

    split_kernel<<<(H1 * H2) / 256, 256>>>(hid_w);
    enc_scan_kernel<<<BB, 256>>>(x, enc_w, enc_b);
    {
        dim3 grid(H2 / BN, (TT * BB) / BM);  // (8, 64)
        gemm2_kernel<<<grid, 256, GEMM_SMEM>>>(hid_b);
    }
    {
        dim3 hgrid(BB, NC / NCH);  // (256, 2)
        head_kernel<<<hgrid, 256, HEAD_SMEM>>>(out_w, out_b, out);
    }
}